// round 1
// baseline (speedup 1.0000x reference)
#include <cuda_runtime.h>
#include <math.h>

#define B_ROWS 262144
#define KC 8
#define DC 32
#define TILE_R 64
#define NTILES (B_ROWS / TILE_R)      // 4096
#define NB1 1184
#define ITEMS_PER_K 1057              // 1 gsum + 32 S1 + 1024 S2
#define NITEMS (KC * ITEMS_PER_K)     // 8456
#define NB2 1024

// ---- scratch (static __device__ globals: sanctioned, no runtime alloc) ----
__device__ float d_partial1[(size_t)NB1 * NITEMS];   // ~40 MB
__device__ float d_moments[NITEMS];
__device__ float d_A[KC * DC * DC];
__device__ float d_mu[KC * DC];
__device__ float d_ck[KC];
__device__ float d_sing[1];
__device__ float d_partial2[NB2 * 2];

// ============================================================
// Pass 1: per-block partial moments  gsum[k], S1[k][e], S2[k][d][e]
// warp w == component k ; lane == column e
// ============================================================
__global__ __launch_bounds__(256) void pass1_kernel(
    const float* __restrict__ feats, const float* __restrict__ gam)
{
    __shared__ __align__(16) float fs[TILE_R * DC];   // 8 KB
    __shared__ __align__(16) float gs[TILE_R * KC];   // 2 KB
    const int tid  = threadIdx.x;
    const int k    = tid >> 5;
    const int lane = tid & 31;

    float acc[DC];
#pragma unroll
    for (int i = 0; i < DC; i++) acc[i] = 0.f;
    float accS1 = 0.f, accG = 0.f;

    for (int tile = blockIdx.x; tile < NTILES; tile += gridDim.x) {
        __syncthreads();
        // stage features tile (64x32 floats = 512 float4)
        const float4* fsrc = (const float4*)(feats + (size_t)tile * TILE_R * DC);
        float4* fdst = (float4*)fs;
        fdst[tid]       = fsrc[tid];
        fdst[tid + 256] = fsrc[tid + 256];
        // stage gamma tile (64x8 floats = 128 float4)
        if (tid < 128) ((float4*)gs)[tid] = ((const float4*)(gam + (size_t)tile * TILE_R * KC))[tid];
        __syncthreads();

#pragma unroll 2
        for (int r = 0; r < TILE_R; r++) {
            float c  = gs[r * KC + k];     // broadcast
            float fe = fs[r * DC + lane];  // coalesced
            float t  = c * fe;
            accG  += c;
            accS1 += t;
            const float4* fr = (const float4*)(fs + r * DC);
#pragma unroll
            for (int db = 0; db < 8; db++) {
                float4 fd = fr[db];        // broadcast LDS.128
                acc[db * 4 + 0] = fmaf(t, fd.x, acc[db * 4 + 0]);
                acc[db * 4 + 1] = fmaf(t, fd.y, acc[db * 4 + 1]);
                acc[db * 4 + 2] = fmaf(t, fd.z, acc[db * 4 + 2]);
                acc[db * 4 + 3] = fmaf(t, fd.w, acc[db * 4 + 3]);
            }
        }
    }

    float* pb = d_partial1 + (size_t)blockIdx.x * NITEMS + k * ITEMS_PER_K;
    if (lane == 0) pb[0] = accG;
    pb[1 + lane] = accS1;
#pragma unroll
    for (int d = 0; d < DC; d++) pb[33 + d * DC + lane] = acc[d];
}

// ============================================================
// Reduce partials over NB1 blocks (deterministic fixed-order sums)
// ============================================================
__global__ void reduce1_kernel()
{
    int i = blockIdx.x * blockDim.x + threadIdx.x;
    if (i >= NITEMS) return;
    float s = 0.f;
    for (int j = 0; j < NB1; j++) s += d_partial1[(size_t)j * NITEMS + i];
    d_moments[i] = s;
}

// ============================================================
// Prep: sigma -> Cholesky -> L^-1 -> A = Sigma^-1, logdet, phi const,
// singularity loss.  One block; warp per k; lane = row/column.
// ============================================================
__global__ __launch_bounds__(256) void prep_kernel()
{
    __shared__ __align__(16) float chol[KC][DC * 33];  // 33.8 KB workspace (sigma -> L -> Z)
    __shared__ float s1s[KC][DC];
    __shared__ float mus[KC][DC];
    __shared__ float singp[KC];

    const int tid  = threadIdx.x;
    const int k    = tid >> 5;
    const int lane = tid & 31;

    const float* mom = d_moments + k * ITEMS_PER_K;
    const float gsum  = mom[0];
    const float denom = gsum + 1e-8f;
    const float s1    = mom[1 + lane];
    const float mu    = s1 / denom;
    s1s[k][lane] = s1;
    mus[k][lane] = mu;
    d_mu[k * DC + lane] = mu;
    __syncwarp();

    // build sigma (lane = column e), track singularity term on diagonal
    float singAcc = 0.f;
#pragma unroll 1
    for (int d = 0; d < DC; d++) {
        float s2  = mom[33 + d * DC + lane];
        float sig = (s2 - mus[k][d] * s1 - s1s[k][d] * mu + gsum * mus[k][d] * mu) / denom;
        if (d == lane) { sig += 1e-6f; singAcc = 1.f / (sig + 1e-8f); }
        chol[k][d * 33 + lane] = sig;
    }
#pragma unroll
    for (int o = 16; o; o >>= 1) singAcc += __shfl_xor_sync(0xffffffffu, singAcc, o);
    if (lane == 0) singp[k] = singAcc;

    // in-place Cholesky, lane i owns row i
    const int i = lane;
    float myDiagLog = 0.f;
    for (int j = 0; j < DC; j++) {
        __syncwarp();
        float s = 0.f;
        if (i >= j) {
            s = chol[k][i * 33 + j];
            for (int m = 0; m < j; m++) s -= chol[k][i * 33 + m] * chol[k][j * 33 + m];
        }
        float sj  = __shfl_sync(0xffffffffu, s, j);
        float Ljj = sqrtf(sj);
        if (i == j) myDiagLog = logf(Ljj);
        if (i >= j) chol[k][i * 33 + j] = (i == j) ? Ljj : s / Ljj;
    }
    __syncwarp();

    // logdet = 2 * sum(log diag)
    float ld = myDiagLog;
#pragma unroll
    for (int o = 16; o; o >>= 1) ld += __shfl_xor_sync(0xffffffffu, ld, o);
    if (lane == 0) {
        float phi = gsum / (float)B_ROWS;
        d_ck[k] = logf(phi + 1e-10f) - 0.5f * (2.f * ld + (float)DC * logf(6.28318f));
    }

    // Z = L^-1, lane c owns column c (register-resident; z[j]=0 for j<c falls
    // out automatically since s starts at 0)
    const int c = lane;
    float z[DC];
#pragma unroll
    for (int ii = 0; ii < DC; ii++) {
        float s = (ii == c) ? 1.f : 0.f;
#pragma unroll
        for (int j = 0; j < ii; j++) s -= chol[k][ii * 33 + j] * z[j];
        z[ii] = s / chol[k][ii * 33 + ii];
    }
    __syncwarp();
    // overwrite workspace with Z (lane writes its own column)
#pragma unroll
    for (int ii = 0; ii < DC; ii++) chol[k][ii * 33 + c] = z[ii];
    __syncwarp();

    // A = Z^T Z ; lane e has z[i] = Z[i][e] in registers, Z[i][d] broadcast
#pragma unroll 1
    for (int d = 0; d < DC; d++) {
        float s = 0.f;
#pragma unroll
        for (int ii = 0; ii < DC; ii++) s = fmaf(chol[k][ii * 33 + d], z[ii], s);
        d_A[k * DC * DC + d * DC + lane] = s;   // symmetric: layout agnostic
    }

    __syncthreads();
    if (tid == 0) {
        float s = 0.f;
        for (int kk = 0; kk < KC; kk++) s += singp[kk];
        d_sing[0] = s;
    }
}

// ============================================================
// Pass 3: per-sample energy (thread per b), online logsumexp over K
// ============================================================
__global__ __launch_bounds__(256) void energy_kernel(
    const float* __restrict__ feats, const float* __restrict__ rec)
{
    __shared__ __align__(16) float As[KC * DC * DC];  // 32 KB
    __shared__ float mus[KC * DC];
    __shared__ float cks[KC];
    __shared__ float red[256];

    const int tid = threadIdx.x;
#pragma unroll
    for (int i = tid; i < KC * DC * DC; i += 256) As[i] = d_A[i];
    if (tid < KC * DC) mus[tid] = d_mu[tid];
    if (tid < KC)      cks[tid] = d_ck[tid];
    __syncthreads();

    const int b = blockIdx.x * 256 + tid;   // grid covers B exactly
    float f[DC];
    const float4* fp = (const float4*)(feats + (size_t)b * DC);
#pragma unroll
    for (int i = 0; i < 8; i++) {
        float4 v = fp[i];
        f[i * 4 + 0] = v.x; f[i * 4 + 1] = v.y; f[i * 4 + 2] = v.z; f[i * 4 + 3] = v.w;
    }

    float m = -INFINITY, ssum = 0.f;
#pragma unroll 1
    for (int k = 0; k < KC; k++) {
        float y[DC];
#pragma unroll
        for (int d = 0; d < DC; d++) y[d] = f[d] - mus[k * DC + d];
        const float* Ak = As + k * DC * DC;
        float mah = 0.f;
#pragma unroll
        for (int db = 0; db < 8; db++) {
            float vx = 0.f, vy = 0.f, vz = 0.f, vw = 0.f;
#pragma unroll
            for (int e = 0; e < DC; e++) {
                float4 a = *(const float4*)(Ak + e * DC + db * 4);  // broadcast LDS.128
                float ye = y[e];
                vx = fmaf(a.x, ye, vx);
                vy = fmaf(a.y, ye, vy);
                vz = fmaf(a.z, ye, vz);
                vw = fmaf(a.w, ye, vw);
            }
            mah = fmaf(vx, y[db * 4 + 0], mah);
            mah = fmaf(vy, y[db * 4 + 1], mah);
            mah = fmaf(vz, y[db * 4 + 2], mah);
            mah = fmaf(vw, y[db * 4 + 3], mah);
        }
        float w = cks[k] - 0.5f * mah;
        if (w > m) { ssum = ssum * expf(m - w) + 1.f; m = w; }
        else       { ssum += expf(w - m); }
    }
    float te = -(m + logf(ssum + 1e-10f));
    if (!isfinite(te)) te = 0.f;
    float re = rec[b];

    // block reductions (deterministic)
    red[tid] = te; __syncthreads();
    for (int s = 128; s; s >>= 1) { if (tid < s) red[tid] += red[tid + s]; __syncthreads(); }
    if (tid == 0) d_partial2[blockIdx.x * 2 + 0] = red[0];
    __syncthreads();
    red[tid] = re; __syncthreads();
    for (int s = 128; s; s >>= 1) { if (tid < s) red[tid] += red[tid + s]; __syncthreads(); }
    if (tid == 0) d_partial2[blockIdx.x * 2 + 1] = red[0];
}

// ============================================================
// Final combine
// ============================================================
__global__ __launch_bounds__(256) void final_kernel(float* __restrict__ out)
{
    __shared__ float red[256];
    const int tid = threadIdx.x;
    float e = 0.f, r = 0.f;
    for (int i = tid; i < NB2; i += 256) {
        e += d_partial2[i * 2 + 0];
        r += d_partial2[i * 2 + 1];
    }
    red[tid] = e; __syncthreads();
    for (int s = 128; s; s >>= 1) { if (tid < s) red[tid] += red[tid + s]; __syncthreads(); }
    float esum = red[0]; __syncthreads();
    red[tid] = r; __syncthreads();
    for (int s = 128; s; s >>= 1) { if (tid < s) red[tid] += red[tid + s]; __syncthreads(); }
    if (tid == 0) {
        float rsum = red[0];
        out[0] = rsum / (float)B_ROWS
               + 0.1f * (esum / (float)B_ROWS)
               + 0.005f * d_sing[0];
    }
}

// ============================================================
extern "C" void kernel_launch(void* const* d_in, const int* in_sizes, int n_in,
                              void* d_out, int out_size)
{
    const float* gamma = nullptr;
    const float* feats = nullptr;
    const float* rec   = nullptr;
    for (int i = 0; i < n_in; i++) {
        if      (in_sizes[i] == B_ROWS * KC) gamma = (const float*)d_in[i];
        else if (in_sizes[i] == B_ROWS * DC) feats = (const float*)d_in[i];
        else if (in_sizes[i] == B_ROWS)      rec   = (const float*)d_in[i];
    }
    pass1_kernel<<<NB1, 256>>>(feats, gamma);
    reduce1_kernel<<<(NITEMS + 255) / 256, 256>>>();
    prep_kernel<<<1, 256>>>();
    energy_kernel<<<NB2, 256>>>(feats, rec);
    final_kernel<<<1, 256>>>((float*)d_out);
}

// round 3
// speedup vs baseline: 1.3758x; 1.3758x over previous
#include <cuda_runtime.h>
#include <math.h>

#define B_ROWS 262144
#define KC 8
#define DC 32
#define TILE_R 64
#define NTILES (B_ROWS / TILE_R)      // 4096
#define NB1 304                        // pass1 grid (2 CTAs/SM * 152)
#define NJ 17                          // triangle offsets 0..16
#define ITEMS_PER_K (1 + 32 + NJ * 32) // 577
#define NITEMS (KC * ITEMS_PER_K)      // 4616
#define EB 1024                        // energy grid

// ---- cp.async helpers ----
__device__ __forceinline__ void cp16(void* smem, const void* gmem) {
    unsigned sa = (unsigned)__cvta_generic_to_shared(smem);
    asm volatile("cp.async.cg.shared.global [%0],[%1],16;" :: "r"(sa), "l"(gmem));
}
#define CP_COMMIT asm volatile("cp.async.commit_group;")
#define CP_WAIT1  asm volatile("cp.async.wait_group 1;")
#define CP_WAIT0  asm volatile("cp.async.wait_group 0;")

// ---- scratch ----
__device__ float d_partial1[(size_t)NB1 * NITEMS];   // ~5.6 MB
__device__ float d_moments[NITEMS];
__device__ float d_Z[KC * DC * DC];                  // L^-1, zeros above diag
__device__ float d_mu[KC * DC];
__device__ float d_ck[KC];
__device__ float d_sing[1];
__device__ float d_partial2[EB * 2];

// ============================================================
// Pass 1: compact triangular moments.
// Warp w: g2=w>>1 covers k in {2g2,2g2+1}; sub=w&1 covers rows r%2==sub.
// Lane e accumulates acc[j] = sum gamma * f[(e+j)%32] * f[e], j=0..16.
// Feature rows duplicated to width 64 so f[(e+j)%32] = frow[e+j] (affine).
// ============================================================
__global__ __launch_bounds__(256, 2) void pass1_kernel(
    const float* __restrict__ feats, const float* __restrict__ gam)
{
    // layout: fs2[2][64*64] | gs[2][512]; combine overlay reuses front NITEMS
    __shared__ __align__(16) float smem[2 * 4096 + 2 * 512];
    float* fsb[2] = { smem,            smem + 4096 };
    float* gsb[2] = { smem + 8192,     smem + 8192 + 512 };

    const int tid  = threadIdx.x;
    const int w    = tid >> 5;
    const int lane = tid & 31;
    const int g2   = w >> 1;
    const int sub  = w & 1;

    float acc0[NJ], acc1[NJ];
#pragma unroll
    for (int j = 0; j < NJ; j++) { acc0[j] = 0.f; acc1[j] = 0.f; }
    float accG0 = 0.f, accG1 = 0.f, accS10 = 0.f, accS11 = 0.f;

    int t = blockIdx.x;
    int cur = 0;
    {   // stage first tile: gmem f4 index q -> row q/8, chunk q%8 -> fs2 slot r*64 + (q%8)*4
        const float* fsrc = feats + (size_t)t * TILE_R * DC;
        int q0 = tid, q1 = tid + 256;
        cp16(fsb[0] + (q0 >> 3) * 64 + (q0 & 7) * 4, fsrc + q0 * 4);
        cp16(fsb[0] + (q1 >> 3) * 64 + (q1 & 7) * 4, fsrc + q1 * 4);
        if (tid < 128) cp16(gsb[0] + tid * 4, gam + (size_t)t * TILE_R * KC + tid * 4);
        CP_COMMIT;
    }

    while (t < NTILES) {
        int tn = t + NB1;
        if (tn < NTILES) {
            const float* fsrc = feats + (size_t)tn * TILE_R * DC;
            int q0 = tid, q1 = tid + 256;
            cp16(fsb[cur ^ 1] + (q0 >> 3) * 64 + (q0 & 7) * 4, fsrc + q0 * 4);
            cp16(fsb[cur ^ 1] + (q1 >> 3) * 64 + (q1 & 7) * 4, fsrc + q1 * 4);
            if (tid < 128) cp16(gsb[cur ^ 1] + tid * 4, gam + (size_t)tn * TILE_R * KC + tid * 4);
            CP_COMMIT;
            CP_WAIT1;
        } else {
            CP_WAIT0;
        }
        __syncthreads();

        float* fs = fsb[cur];
        const float* gs = gsb[cur];

        // duplicate each row's first 32 floats into [32..64)
        {
            int q0 = tid, q1 = tid + 256;           // float4 index within 512
            float4* fp = (float4*)fs;
            int r0 = q0 >> 3, c0 = q0 & 7;
            int r1 = q1 >> 3, c1 = q1 & 7;
            fp[r0 * 16 + 8 + c0] = fp[r0 * 16 + c0];
            fp[r1 * 16 + 8 + c1] = fp[r1 * 16 + c1];
        }
        __syncthreads();

#pragma unroll 2
        for (int rr = 0; rr < 32; rr++) {
            int r = rr * 2 + sub;
            const float* frow = fs + r * 64;
            float2 gv = *(const float2*)(gs + r * KC + g2 * 2);   // broadcast LDS.64
            float fe = frow[lane];
            float t0 = gv.x * fe, t1 = gv.y * fe;
            accG0 += gv.x; accG1 += gv.y;
            accS10 += t0;  accS11 += t1;
            acc0[0] = fmaf(t0, fe, acc0[0]);
            acc1[0] = fmaf(t1, fe, acc1[0]);
#pragma unroll
            for (int j = 1; j < NJ; j++) {
                float fr = frow[lane + j];          // affine, conflict-free
                acc0[j] = fmaf(t0, fr, acc0[j]);
                acc1[j] = fmaf(t1, fr, acc1[j]);
            }
        }
        __syncthreads();
        t = tn; cur ^= 1;
    }

    // ---- in-block combine: smem reused as red[8][577] ----
    for (int i = tid; i < NITEMS; i += 256) smem[i] = 0.f;
    __syncthreads();
    for (int s = 0; s < 2; s++) {
        if (sub == s) {
            float* rk0 = smem + (2 * g2) * ITEMS_PER_K;
            float* rk1 = smem + (2 * g2 + 1) * ITEMS_PER_K;
            if (lane == 0) { rk0[0] += accG0; rk1[0] += accG1; }
            rk0[1 + lane] += accS10;
            rk1[1 + lane] += accS11;
#pragma unroll
            for (int j = 0; j < NJ; j++) {
                rk0[33 + j * 32 + lane] += acc0[j];
                rk1[33 + j * 32 + lane] += acc1[j];
            }
        }
        __syncthreads();
    }
    for (int i = tid; i < NITEMS; i += 256)
        d_partial1[(size_t)blockIdx.x * NITEMS + i] = smem[i];
}

// ============================================================
// Reduce partials over NB1 blocks (deterministic fixed-order sums)
// ============================================================
__global__ void reduce1_kernel()
{
    int i = blockIdx.x * blockDim.x + threadIdx.x;
    if (i >= NITEMS) return;
    float s = 0.f;
#pragma unroll 4
    for (int j = 0; j < NB1; j++) s += d_partial1[(size_t)j * NITEMS + i];
    d_moments[i] = s;
}

// ============================================================
// Prep: sigma (from compact S2) -> Cholesky -> Z=L^-1 (stored), logdet,
// phi const, singularity loss.  One block; warp per k.
// ============================================================
__global__ __launch_bounds__(256) void prep_kernel()
{
    __shared__ __align__(16) float chol[KC][DC * 33];
    __shared__ float s1s[KC][DC];
    __shared__ float mus[KC][DC];
    __shared__ float singp[KC];

    const int tid  = threadIdx.x;
    const int k    = tid >> 5;
    const int lane = tid & 31;

    const float* mom = d_moments + k * ITEMS_PER_K;
    const float gsum  = mom[0];
    const float denom = gsum + 1e-8f;
    const float s1    = mom[1 + lane];
    const float mu    = s1 / denom;
    s1s[k][lane] = s1;
    mus[k][lane] = mu;
    d_mu[k * DC + lane] = mu;
    __syncwarp();

    // build sigma column `lane`: S2[d][lane] from compact triangle
    float singAcc = 0.f;
#pragma unroll 1
    for (int d = 0; d < DC; d++) {
        int j = (d - lane) & 31;
        float s2;
        if (j <= 16) s2 = mom[33 + j * 32 + lane];
        else         s2 = mom[33 + ((lane - d) & 31) * 32 + d];
        float sig = (s2 - mus[k][d] * s1 - s1s[k][d] * mu + gsum * mus[k][d] * mu) / denom;
        if (d == lane) { sig += 1e-6f; singAcc = 1.f / (sig + 1e-8f); }
        chol[k][d * 33 + lane] = sig;
    }
#pragma unroll
    for (int o = 16; o; o >>= 1) singAcc += __shfl_xor_sync(0xffffffffu, singAcc, o);
    if (lane == 0) singp[k] = singAcc;

    // in-place Cholesky, lane i owns row i
    const int i = lane;
    float myDiagLog = 0.f;
    for (int j = 0; j < DC; j++) {
        __syncwarp();
        float s = 0.f;
        if (i >= j) {
            s = chol[k][i * 33 + j];
            for (int m = 0; m < j; m++) s -= chol[k][i * 33 + m] * chol[k][j * 33 + m];
        }
        float sj  = __shfl_sync(0xffffffffu, s, j);
        float Ljj = sqrtf(sj);
        if (i == j) myDiagLog = logf(Ljj);
        if (i >= j) chol[k][i * 33 + j] = (i == j) ? Ljj : s / Ljj;
    }
    __syncwarp();

    float ld = myDiagLog;
#pragma unroll
    for (int o = 16; o; o >>= 1) ld += __shfl_xor_sync(0xffffffffu, ld, o);
    if (lane == 0) {
        float phi = gsum / (float)B_ROWS;
        d_ck[k] = logf(phi + 1e-10f) - 0.5f * (2.f * ld + (float)DC * logf(6.28318f));
    }

    // Z = L^-1, lane c owns column c (zeros above diagonal fall out)
    const int c = lane;
    float z[DC];
#pragma unroll
    for (int ii = 0; ii < DC; ii++) {
        float s = (ii == c) ? 1.f : 0.f;
#pragma unroll
        for (int j = 0; j < ii; j++) s -= chol[k][ii * 33 + j] * z[j];
        z[ii] = s / chol[k][ii * 33 + ii];
    }
    __syncwarp();
    // store full Z row-major (upper entries are exact zeros)
#pragma unroll
    for (int ii = 0; ii < DC; ii++)
        d_Z[k * DC * DC + ii * DC + lane] = z[ii];

    __syncthreads();
    if (tid == 0) {
        float s = 0.f;
        for (int kk = 0; kk < KC; kk++) s += singp[kk];
        d_sing[0] = s;
    }
}

// ============================================================
// Pass 3: energy.  mah = ||Z y||^2 via triangular matvec (zero-padded rows).
// ============================================================
__global__ __launch_bounds__(256, 2) void energy_kernel(
    const float* __restrict__ feats, const float* __restrict__ rec)
{
    __shared__ __align__(16) float Zs[KC * DC * DC];   // 32 KB
    __shared__ __align__(16) float mus[KC * DC];
    __shared__ float cks[KC];
    __shared__ float red[256];

    const int tid = threadIdx.x;
    for (int i = tid; i < KC * DC * DC; i += 256) Zs[i] = d_Z[i];
    if (tid < KC * DC) mus[tid] = d_mu[tid];
    if (tid < KC)      cks[tid] = d_ck[tid];
    __syncthreads();

    const int b = blockIdx.x * 256 + tid;
    float f[DC];
    const float4* fp = (const float4*)(feats + (size_t)b * DC);
#pragma unroll
    for (int i = 0; i < 8; i++) {
        float4 v = fp[i];
        f[i * 4 + 0] = v.x; f[i * 4 + 1] = v.y; f[i * 4 + 2] = v.z; f[i * 4 + 3] = v.w;
    }

    float m = -INFINITY, ssum = 0.f;
#pragma unroll 1
    for (int k = 0; k < KC; k++) {
        const float* Zk = Zs + k * DC * DC;
        const float* muk = mus + k * DC;
        float y[DC];
#pragma unroll
        for (int d = 0; d < DC; d++) y[d] = f[d] - muk[d];

        float mah = 0.f;
#pragma unroll
        for (int i = 0; i < DC; i++) {
            const float4* zr = (const float4*)(Zk + i * DC);
            float wx = 0.f, wy = 0.f, wz = 0.f, ww = 0.f;
#pragma unroll
            for (int c = 0; c <= (i >> 2); c++) {
                float4 zv = zr[c];                  // broadcast LDS.128
                wx = fmaf(zv.x, y[4 * c + 0], wx);
                wy = fmaf(zv.y, y[4 * c + 1], wy);
                wz = fmaf(zv.z, y[4 * c + 2], wz);
                ww = fmaf(zv.w, y[4 * c + 3], ww);
            }
            float wsum = (wx + wy) + (wz + ww);
            mah = fmaf(wsum, wsum, mah);
        }
        float wlp = cks[k] - 0.5f * mah;
        if (wlp > m) { ssum = ssum * expf(m - wlp) + 1.f; m = wlp; }
        else         { ssum += expf(wlp - m); }
    }
    float te = -(m + logf(ssum + 1e-10f));
    if (!isfinite(te)) te = 0.f;
    float re = rec[b];

    red[tid] = te; __syncthreads();
    for (int s = 128; s; s >>= 1) { if (tid < s) red[tid] += red[tid + s]; __syncthreads(); }
    if (tid == 0) d_partial2[blockIdx.x * 2 + 0] = red[0];
    __syncthreads();
    red[tid] = re; __syncthreads();
    for (int s = 128; s; s >>= 1) { if (tid < s) red[tid] += red[tid + s]; __syncthreads(); }
    if (tid == 0) d_partial2[blockIdx.x * 2 + 1] = red[0];
}

// ============================================================
// Final combine
// ============================================================
__global__ __launch_bounds__(256) void final_kernel(float* __restrict__ out)
{
    __shared__ float red[256];
    const int tid = threadIdx.x;
    float e = 0.f, r = 0.f;
    for (int i = tid; i < EB; i += 256) {
        e += d_partial2[i * 2 + 0];
        r += d_partial2[i * 2 + 1];
    }
    red[tid] = e; __syncthreads();
    for (int s = 128; s; s >>= 1) { if (tid < s) red[tid] += red[tid + s]; __syncthreads(); }
    float esum = red[0]; __syncthreads();
    red[tid] = r; __syncthreads();
    for (int s = 128; s; s >>= 1) { if (tid < s) red[tid] += red[tid + s]; __syncthreads(); }
    if (tid == 0) {
        float rsum = red[0];
        out[0] = rsum / (float)B_ROWS
               + 0.1f * (esum / (float)B_ROWS)
               + 0.005f * d_sing[0];
    }
}

// ============================================================
extern "C" void kernel_launch(void* const* d_in, const int* in_sizes, int n_in,
                              void* d_out, int out_size)
{
    const float* gamma = nullptr;
    const float* feats = nullptr;
    const float* rec   = nullptr;
    for (int i = 0; i < n_in; i++) {
        if      (in_sizes[i] == B_ROWS * KC) gamma = (const float*)d_in[i];
        else if (in_sizes[i] == B_ROWS * DC) feats = (const float*)d_in[i];
        else if (in_sizes[i] == B_ROWS)      rec   = (const float*)d_in[i];
    }
    pass1_kernel<<<NB1, 256>>>(feats, gamma);
    reduce1_kernel<<<(NITEMS + 255) / 256, 256>>>();
    prep_kernel<<<1, 256>>>();
    energy_kernel<<<EB, 256>>>(feats, rec);
    final_kernel<<<1, 256>>>((float*)d_out);
}

// round 4
// speedup vs baseline: 1.7015x; 1.2368x over previous
#include <cuda_runtime.h>
#include <math.h>

#define B_ROWS 262144
#define KC 8
#define DC 32
#define TILE_R 64
#define NTILES (B_ROWS / TILE_R)      // 4096
#define NB1 304                        // pass1 grid (2 CTAs/SM * 152)
#define NJ 17                          // triangle offsets 0..16
#define ITEMS_PER_K (1 + 32 + NJ * 32) // 577
#define NITEMS (KC * ITEMS_PER_K)      // 4616
#define EB 512                         // energy grid (512 samples/block)

// ---- cp.async helpers ----
__device__ __forceinline__ void cp16(void* smem, const void* gmem) {
    unsigned sa = (unsigned)__cvta_generic_to_shared(smem);
    asm volatile("cp.async.cg.shared.global [%0],[%1],16;" :: "r"(sa), "l"(gmem));
}
#define CP_COMMIT asm volatile("cp.async.commit_group;")
#define CP_WAIT1  asm volatile("cp.async.wait_group 1;")
#define CP_WAIT0  asm volatile("cp.async.wait_group 0;")

// ---- scratch ----
__device__ float d_partial1[(size_t)NB1 * NITEMS];   // ~5.6 MB
__device__ float d_moments[NITEMS];
__device__ float d_Z[KC * DC * DC];                  // L^-1, zeros above diag
__device__ float d_u[KC * DC];                       // Z^T (Z mu)
__device__ float d_ck[KC];                           // log phi - 0.5(logdet + D log2pi + c2)
__device__ float d_sing[1];
__device__ float d_partial2[EB * 2];

// ============================================================
// Pass 1: compact triangular moments.
// Warp w: quad q=w>>2 covers k in {4q..4q+3}; sub=w&3 covers rows r%4==sub.
// Lane e accumulates acc[m][j] = sum gamma_{4q+m} * f[e] * f[(e+j)%32], j=0..16.
// Feature rows duplicated to width 64 so f[(e+j)%32] = frow[e+j] (affine).
// ============================================================
__global__ __launch_bounds__(256, 2) void pass1_kernel(
    const float* __restrict__ feats, const float* __restrict__ gam)
{
    // layout: fs2[2][64*64] | gs[2][512]; combine overlay reuses front NITEMS
    __shared__ __align__(16) float smem[2 * 4096 + 2 * 512];
    float* fsb[2] = { smem,        smem + 4096 };
    float* gsb[2] = { smem + 8192, smem + 8192 + 512 };

    const int tid  = threadIdx.x;
    const int w    = tid >> 5;
    const int lane = tid & 31;
    const int q    = w >> 2;     // k-quad 0..1
    const int sub  = w & 3;      // row subset

    float acc[4][NJ];
#pragma unroll
    for (int m = 0; m < 4; m++)
#pragma unroll
        for (int j = 0; j < NJ; j++) acc[m][j] = 0.f;
    float accG[4] = {0.f, 0.f, 0.f, 0.f};
    float accS1[4] = {0.f, 0.f, 0.f, 0.f};

    int t = blockIdx.x;
    int cur = 0;
    {   // stage first tile: f4 index qq -> row qq/8, chunk qq%8 -> slot r*64 + (qq%8)*4
        const float* fsrc = feats + (size_t)t * TILE_R * DC;
        int q0 = tid, q1 = tid + 256;
        cp16(fsb[0] + (q0 >> 3) * 64 + (q0 & 7) * 4, fsrc + q0 * 4);
        cp16(fsb[0] + (q1 >> 3) * 64 + (q1 & 7) * 4, fsrc + q1 * 4);
        if (tid < 128) cp16(gsb[0] + tid * 4, gam + (size_t)t * TILE_R * KC + tid * 4);
        CP_COMMIT;
    }

    while (t < NTILES) {
        int tn = t + NB1;
        if (tn < NTILES) {
            const float* fsrc = feats + (size_t)tn * TILE_R * DC;
            int q0 = tid, q1 = tid + 256;
            cp16(fsb[cur ^ 1] + (q0 >> 3) * 64 + (q0 & 7) * 4, fsrc + q0 * 4);
            cp16(fsb[cur ^ 1] + (q1 >> 3) * 64 + (q1 & 7) * 4, fsrc + q1 * 4);
            if (tid < 128) cp16(gsb[cur ^ 1] + tid * 4, gam + (size_t)tn * TILE_R * KC + tid * 4);
            CP_COMMIT;
            CP_WAIT1;
        } else {
            CP_WAIT0;
        }
        __syncthreads();

        float* fs = fsb[cur];
        const float* gs = gsb[cur];

        // duplicate each row's first 32 floats into [32..64)
        {
            int q0 = tid, q1 = tid + 256;
            float4* fp = (float4*)fs;
            int r0 = q0 >> 3, c0 = q0 & 7;
            int r1 = q1 >> 3, c1 = q1 & 7;
            fp[r0 * 16 + 8 + c0] = fp[r0 * 16 + c0];
            fp[r1 * 16 + 8 + c1] = fp[r1 * 16 + c1];
        }
        __syncthreads();

#pragma unroll 2
        for (int rr = 0; rr < 16; rr++) {
            int r = rr * 4 + sub;
            const float* frow = fs + r * 64;
            float4 gv = *(const float4*)(gs + r * KC + q * 4);    // broadcast LDS.128
            float fe = frow[lane];
            float t0 = gv.x * fe, t1 = gv.y * fe, t2 = gv.z * fe, t3 = gv.w * fe;
            accG[0] += gv.x; accG[1] += gv.y; accG[2] += gv.z; accG[3] += gv.w;
            accS1[0] += t0; accS1[1] += t1; accS1[2] += t2; accS1[3] += t3;
            acc[0][0] = fmaf(t0, fe, acc[0][0]);
            acc[1][0] = fmaf(t1, fe, acc[1][0]);
            acc[2][0] = fmaf(t2, fe, acc[2][0]);
            acc[3][0] = fmaf(t3, fe, acc[3][0]);
#pragma unroll
            for (int j = 1; j < NJ; j++) {
                float fr = frow[lane + j];          // affine, conflict-free
                acc[0][j] = fmaf(t0, fr, acc[0][j]);
                acc[1][j] = fmaf(t1, fr, acc[1][j]);
                acc[2][j] = fmaf(t2, fr, acc[2][j]);
                acc[3][j] = fmaf(t3, fr, acc[3][j]);
            }
        }
        __syncthreads();
        t = tn; cur ^= 1;
    }

    // ---- in-block combine: smem reused as red[8][577] ----
    for (int i = tid; i < NITEMS; i += 256) smem[i] = 0.f;
    __syncthreads();
    for (int s = 0; s < 4; s++) {
        if (sub == s) {
#pragma unroll
            for (int m = 0; m < 4; m++) {
                float* rk = smem + (4 * q + m) * ITEMS_PER_K;
                if (lane == 0) rk[0] += accG[m];
                rk[1 + lane] += accS1[m];
#pragma unroll
                for (int j = 0; j < NJ; j++)
                    rk[33 + j * 32 + lane] += acc[m][j];
            }
        }
        __syncthreads();
    }
    for (int i = tid; i < NITEMS; i += 256)
        d_partial1[(size_t)blockIdx.x * NITEMS + i] = smem[i];
}

// ============================================================
// Reduce partials over NB1 blocks (deterministic fixed-order sums)
// ============================================================
__global__ void reduce1_kernel()
{
    int i = blockIdx.x * blockDim.x + threadIdx.x;
    if (i >= NITEMS) return;
    float s = 0.f;
#pragma unroll 4
    for (int j = 0; j < NB1; j++) s += d_partial1[(size_t)j * NITEMS + i];
    d_moments[i] = s;
}

// ============================================================
// Prep: sigma -> Cholesky -> Z=L^-1 ; t=Z mu, u=Z^T t, c2=||t||^2 folded
// into ck.  One block; warp per k.
// ============================================================
__global__ __launch_bounds__(256) void prep_kernel()
{
    __shared__ __align__(16) float chol[KC][DC * 33];
    __shared__ float s1s[KC][DC];
    __shared__ float mus[KC][DC];
    __shared__ float ts[KC][DC];
    __shared__ float singp[KC];

    const int tid  = threadIdx.x;
    const int k    = tid >> 5;
    const int lane = tid & 31;

    const float* mom = d_moments + k * ITEMS_PER_K;
    const float gsum  = mom[0];
    const float denom = gsum + 1e-8f;
    const float s1    = mom[1 + lane];
    const float mu    = s1 / denom;
    s1s[k][lane] = s1;
    mus[k][lane] = mu;
    __syncwarp();

    // build sigma column `lane`: S2[d][lane] from compact triangle
    float singAcc = 0.f;
#pragma unroll 1
    for (int d = 0; d < DC; d++) {
        int j = (d - lane) & 31;
        float s2;
        if (j <= 16) s2 = mom[33 + j * 32 + lane];
        else         s2 = mom[33 + ((lane - d) & 31) * 32 + d];
        float sig = (s2 - mus[k][d] * s1 - s1s[k][d] * mu + gsum * mus[k][d] * mu) / denom;
        if (d == lane) { sig += 1e-6f; singAcc = 1.f / (sig + 1e-8f); }
        chol[k][d * 33 + lane] = sig;
    }
#pragma unroll
    for (int o = 16; o; o >>= 1) singAcc += __shfl_xor_sync(0xffffffffu, singAcc, o);
    if (lane == 0) singp[k] = singAcc;

    // in-place Cholesky, lane i owns row i
    const int i = lane;
    float myDiagLog = 0.f;
    for (int j = 0; j < DC; j++) {
        __syncwarp();
        float s = 0.f;
        if (i >= j) {
            s = chol[k][i * 33 + j];
            for (int m = 0; m < j; m++) s -= chol[k][i * 33 + m] * chol[k][j * 33 + m];
        }
        float sj  = __shfl_sync(0xffffffffu, s, j);
        float Ljj = sqrtf(sj);
        if (i == j) myDiagLog = logf(Ljj);
        if (i >= j) chol[k][i * 33 + j] = (i == j) ? Ljj : s / Ljj;
    }
    __syncwarp();

    float ld = myDiagLog;
#pragma unroll
    for (int o = 16; o; o >>= 1) ld += __shfl_xor_sync(0xffffffffu, ld, o);

    // Z = L^-1, lane c owns column c
    const int c = lane;
    float z[DC];
#pragma unroll
    for (int ii = 0; ii < DC; ii++) {
        float s = (ii == c) ? 1.f : 0.f;
#pragma unroll
        for (int j = 0; j < ii; j++) s -= chol[k][ii * 33 + j] * z[j];
        z[ii] = s / chol[k][ii * 33 + ii];
    }
    __syncwarp();
    // overwrite workspace with Z and store to gmem
#pragma unroll
    for (int ii = 0; ii < DC; ii++) {
        chol[k][ii * 33 + c] = z[ii];
        d_Z[k * DC * DC + ii * DC + c] = z[ii];
    }
    __syncwarp();

    // t_i = sum_j Z[i][j] mu[j]   (lane i owns row i)
    float tval = 0.f;
#pragma unroll
    for (int j = 0; j < DC; j++) tval = fmaf(chol[k][lane * 33 + j], mus[k][j], tval);
    ts[k][lane] = tval;
    __syncwarp();

    // c2 = sum t^2
    float c2 = tval * tval;
#pragma unroll
    for (int o = 16; o; o >>= 1) c2 += __shfl_xor_sync(0xffffffffu, c2, o);

    // u_c = sum_i Z[i][c] t_i  (lane c has column c in z[])
    float uval = 0.f;
#pragma unroll
    for (int ii = 0; ii < DC; ii++) uval = fmaf(z[ii], ts[k][ii], uval);
    d_u[k * DC + c] = uval;

    if (lane == 0) {
        float phi = gsum / (float)B_ROWS;
        d_ck[k] = logf(phi + 1e-10f)
                - 0.5f * (2.f * ld + (float)DC * logf(6.28318f) + c2);
    }

    __syncthreads();
    if (tid == 0) {
        float s = 0.f;
        for (int kk = 0; kk < KC; kk++) s += singp[kk];
        d_sing[0] = s;
    }
}

// ============================================================
// Pass 3: energy.  2 samples/thread.
// wlp = ck' + <f,u> - 0.5*||Z f||^2   (mu folded into u, c2 into ck')
// ============================================================
__global__ __launch_bounds__(256, 2) void energy_kernel(
    const float* __restrict__ feats, const float* __restrict__ rec)
{
    __shared__ __align__(16) float Zs[KC * DC * DC];   // 32 KB
    __shared__ __align__(16) float us[KC * DC];
    __shared__ float cks[KC];
    __shared__ float red[256];

    const int tid = threadIdx.x;
    for (int i = tid; i < KC * DC * DC; i += 256) Zs[i] = d_Z[i];
    if (tid < KC * DC) us[tid] = d_u[tid];
    if (tid < KC)      cks[tid] = d_ck[tid];
    __syncthreads();

    const int b0 = blockIdx.x * 512 + tid;
    const int b1 = b0 + 256;

    float f0[DC], f1[DC];
    {
        const float4* p0 = (const float4*)(feats + (size_t)b0 * DC);
        const float4* p1 = (const float4*)(feats + (size_t)b1 * DC);
#pragma unroll
        for (int i = 0; i < 8; i++) {
            float4 a = p0[i];
            f0[i * 4 + 0] = a.x; f0[i * 4 + 1] = a.y; f0[i * 4 + 2] = a.z; f0[i * 4 + 3] = a.w;
            float4 b = p1[i];
            f1[i * 4 + 0] = b.x; f1[i * 4 + 1] = b.y; f1[i * 4 + 2] = b.z; f1[i * 4 + 3] = b.w;
        }
    }

    float m0 = -INFINITY, ss0 = 0.f;
    float m1 = -INFINITY, ss1 = 0.f;

#pragma unroll 1
    for (int k = 0; k < KC; k++) {
        const float4* Zr = (const float4*)(Zs + k * DC * DC);
        const float4* uk = (const float4*)(us + k * DC);

        float dot0 = 0.f, dot1 = 0.f;
#pragma unroll
        for (int qd = 0; qd < 8; qd++) {
            float4 u4 = uk[qd];                    // broadcast LDS.128
            dot0 = fmaf(u4.x, f0[4 * qd + 0], dot0);
            dot0 = fmaf(u4.y, f0[4 * qd + 1], dot0);
            dot0 = fmaf(u4.z, f0[4 * qd + 2], dot0);
            dot0 = fmaf(u4.w, f0[4 * qd + 3], dot0);
            dot1 = fmaf(u4.x, f1[4 * qd + 0], dot1);
            dot1 = fmaf(u4.y, f1[4 * qd + 1], dot1);
            dot1 = fmaf(u4.z, f1[4 * qd + 2], dot1);
            dot1 = fmaf(u4.w, f1[4 * qd + 3], dot1);
        }

        float sv0 = 0.f, sv1 = 0.f;
#pragma unroll
        for (int i = 0; i < DC; i++) {
            const float4* zrow = Zr + i * 8;
            float ax0 = 0.f, ay0 = 0.f, az0 = 0.f, aw0 = 0.f;
            float ax1 = 0.f, ay1 = 0.f, az1 = 0.f, aw1 = 0.f;
#pragma unroll
            for (int c = 0; c <= (i >> 2); c++) {
                float4 zv = zrow[c];               // broadcast LDS.128
                ax0 = fmaf(zv.x, f0[4 * c + 0], ax0);
                ay0 = fmaf(zv.y, f0[4 * c + 1], ay0);
                az0 = fmaf(zv.z, f0[4 * c + 2], az0);
                aw0 = fmaf(zv.w, f0[4 * c + 3], aw0);
                ax1 = fmaf(zv.x, f1[4 * c + 0], ax1);
                ay1 = fmaf(zv.y, f1[4 * c + 1], ay1);
                az1 = fmaf(zv.z, f1[4 * c + 2], az1);
                aw1 = fmaf(zv.w, f1[4 * c + 3], aw1);
            }
            float w0 = (ax0 + ay0) + (az0 + aw0);
            float w1 = (ax1 + ay1) + (az1 + aw1);
            sv0 = fmaf(w0, w0, sv0);
            sv1 = fmaf(w1, w1, sv1);
        }
        float wlp0 = cks[k] + dot0 - 0.5f * sv0;
        float wlp1 = cks[k] + dot1 - 0.5f * sv1;
        if (wlp0 > m0) { ss0 = ss0 * expf(m0 - wlp0) + 1.f; m0 = wlp0; } else { ss0 += expf(wlp0 - m0); }
        if (wlp1 > m1) { ss1 = ss1 * expf(m1 - wlp1) + 1.f; m1 = wlp1; } else { ss1 += expf(wlp1 - m1); }
    }

    float te0 = -(m0 + logf(ss0 + 1e-10f));
    float te1 = -(m1 + logf(ss1 + 1e-10f));
    if (!isfinite(te0)) te0 = 0.f;
    if (!isfinite(te1)) te1 = 0.f;
    float resum = rec[b0] + rec[b1];

    red[tid] = te0 + te1; __syncthreads();
    for (int s = 128; s; s >>= 1) { if (tid < s) red[tid] += red[tid + s]; __syncthreads(); }
    if (tid == 0) d_partial2[blockIdx.x * 2 + 0] = red[0];
    __syncthreads();
    red[tid] = resum; __syncthreads();
    for (int s = 128; s; s >>= 1) { if (tid < s) red[tid] += red[tid + s]; __syncthreads(); }
    if (tid == 0) d_partial2[blockIdx.x * 2 + 1] = red[0];
}

// ============================================================
// Final combine
// ============================================================
__global__ __launch_bounds__(256) void final_kernel(float* __restrict__ out)
{
    __shared__ float red[256];
    const int tid = threadIdx.x;
    float e = 0.f, r = 0.f;
    for (int i = tid; i < EB; i += 256) {
        e += d_partial2[i * 2 + 0];
        r += d_partial2[i * 2 + 1];
    }
    red[tid] = e; __syncthreads();
    for (int s = 128; s; s >>= 1) { if (tid < s) red[tid] += red[tid + s]; __syncthreads(); }
    float esum = red[0]; __syncthreads();
    red[tid] = r; __syncthreads();
    for (int s = 128; s; s >>= 1) { if (tid < s) red[tid] += red[tid + s]; __syncthreads(); }
    if (tid == 0) {
        float rsum = red[0];
        out[0] = rsum / (float)B_ROWS
               + 0.1f * (esum / (float)B_ROWS)
               + 0.005f * d_sing[0];
    }
}

// ============================================================
extern "C" void kernel_launch(void* const* d_in, const int* in_sizes, int n_in,
                              void* d_out, int out_size)
{
    const float* gamma = nullptr;
    const float* feats = nullptr;
    const float* rec   = nullptr;
    for (int i = 0; i < n_in; i++) {
        if      (in_sizes[i] == B_ROWS * KC) gamma = (const float*)d_in[i];
        else if (in_sizes[i] == B_ROWS * DC) feats = (const float*)d_in[i];
        else if (in_sizes[i] == B_ROWS)      rec   = (const float*)d_in[i];
    }
    pass1_kernel<<<NB1, 256>>>(feats, gamma);
    reduce1_kernel<<<(NITEMS + 255) / 256, 256>>>();
    prep_kernel<<<1, 256>>>();
    energy_kernel<<<EB, 256>>>(feats, rec);
    final_kernel<<<1, 256>>>((float*)d_out);
}